// round 4
// baseline (speedup 1.0000x reference)
#include <cuda_runtime.h>
#include <cuda_bf16.h>

// NEP descriptor R3: counting-sort edges by destination atom, then
// register-resident gather-reduce (no wide atomic scatter, no scratch).

#define NUM_TYPES 4
#define NR 11          // N_MAX_RADIAL+1 (= BASIS_RADIAL+1)
#define NA 7           // N_MAX_ANGULAR+1
#define BA 9           // BASIS_ANGULAR+1
#define MAX_ATOMS 50176
#define EMAX 1000000

__device__ int    g_count[MAX_ATOMS];
__device__ int    g_offset[MAX_ATOMS + 1];
__device__ int    g_cursor[MAX_ATOMS];
__device__ float4 g_ra[EMAX];   // (x, cut, ux, uy)
__device__ float2 g_rb[EMAX];   // (uz, pair-as-bits)
__device__ int    g_idx64;      // 1 if edge_index/types are int64

__global__ void detect_dtype_kernel(const int* __restrict__ ei32) {
    // int64 indices < 2^31 viewed as int32 pairs: every odd word is 0.
    int ok = 1;
    #pragma unroll
    for (int k = 1; k < 32; k += 2)
        if (ei32[k] != 0) ok = 0;
    g_idx64 = ok;
}

__global__ void zero_counts_kernel(int N) {
    int i = blockIdx.x * blockDim.x + threadIdx.x;
    if (i < N) g_count[i] = 0;
}

__global__ void hist_kernel(const void* __restrict__ edge_index, int E) {
    int e = blockIdx.x * blockDim.x + threadIdx.x;
    if (e >= E) return;
    int row = g_idx64 ? (int)((const long long*)edge_index)[e]
                      : ((const int*)edge_index)[e];
    atomicAdd(&g_count[row], 1);
}

// Single-block exclusive scan over N counts -> g_offset[0..N], g_cursor copy.
__global__ __launch_bounds__(1024)
void scan_kernel(int N) {
    __shared__ int warp_sums[32];
    int t = threadIdx.x;
    int lane = t & 31, wid = t >> 5;
    int chunk = (N + 1023) >> 10;
    int lo = t * chunk;
    int hi = min(lo + chunk, N);
    if (lo > N) lo = N;

    int sum = 0;
    for (int i = lo; i < hi; i++) sum += g_count[i];

    // inclusive warp scan of per-thread sums
    int v = sum;
    #pragma unroll
    for (int o = 1; o < 32; o <<= 1) {
        int n = __shfl_up_sync(0xFFFFFFFFu, v, o);
        if (lane >= o) v += n;
    }
    if (lane == 31) warp_sums[wid] = v;
    __syncthreads();
    if (wid == 0) {
        int w = warp_sums[lane];
        #pragma unroll
        for (int o = 1; o < 32; o <<= 1) {
            int n = __shfl_up_sync(0xFFFFFFFFu, w, o);
            if (lane >= o) w += n;
        }
        warp_sums[lane] = w;
    }
    __syncthreads();

    int base = v - sum + (wid > 0 ? warp_sums[wid - 1] : 0);
    int run = base;
    for (int i = lo; i < hi; i++) {
        g_offset[i] = run;
        g_cursor[i] = run;
        run += g_count[i];
    }
    if (t == 0) g_offset[N] = warp_sums[31];
}

__global__ __launch_bounds__(256)
void scatter_kernel(const void* __restrict__ edge_index,
                    const float* __restrict__ edge_length,
                    const float* __restrict__ edge_vec,
                    const void* __restrict__ types,
                    int E)
{
    int e = blockIdx.x * blockDim.x + threadIdx.x;
    if (e >= E) return;

    int row, col, ti, tj;
    if (g_idx64) {
        const long long* ei = (const long long*)edge_index;
        const long long* ty = (const long long*)types;
        row = (int)ei[e];
        col = (int)ei[E + e];
        ti = (int)ty[row]; tj = (int)ty[col];
    } else {
        const int* ei = (const int*)edge_index;
        const int* ty = (const int*)types;
        row = ei[e];
        col = ei[E + e];
        ti = ty[row]; tj = ty[col];
    }
    int pair = ti * NUM_TYPES + tj;

    float d = edge_length[e];
    float s = d * 0.2f;                    // d / CUTOFF
    float x = 2.0f * s - 1.0f;
    float denom = 1.0f - s * s;
    float cut = (s < 1.0f) ? expf(1.0f - 1.0f / denom) : 0.0f;

    float vx = edge_vec[e * 3 + 0];
    float vy = edge_vec[e * 3 + 1];
    float vz = edge_vec[e * 3 + 2];
    float inv = 1.0f / fmaxf(d, 1e-8f);

    int pos = atomicAdd(&g_cursor[row], 1);
    g_ra[pos] = make_float4(x, cut, vx * inv, vy * inv);
    g_rb[pos] = make_float2(vz * inv, __int_as_float(pair));
}

__global__ __launch_bounds__(128)
void gather_kernel(float* __restrict__ out,
                   const float* __restrict__ c_radial,
                   const float* __restrict__ c_angular,
                   int N)
{
    // Shared coefficient tables, pair-minor: lanes with different pairs hit
    // distinct banks; same pair -> broadcast. Conflict-free.
    __shared__ float crs[NR * NR * 16];   // [(b*11+n)*16 + pair]
    __shared__ float cas[BA * NA * 16];   // [(b*7+n)*16 + pair]

    for (int i = threadIdx.x; i < 16 * NR * NR; i += blockDim.x) {
        int pair = i / (NR * NR);
        int nb   = i % (NR * NR);
        int n = nb / NR, b = nb % NR;
        crs[(b * NR + n) * 16 + pair] = c_radial[i];
    }
    for (int i = threadIdx.x; i < 16 * NA * BA; i += blockDim.x) {
        int pair = i / (NA * BA);
        int nb   = i % (NA * BA);
        int n = nb / BA, b = nb % BA;
        cas[(b * NA + n) * 16 + pair] = c_angular[i];
    }
    __syncthreads();

    int a = blockIdx.x * blockDim.x + threadIdx.x;
    if (a >= N) return;

    int start = g_offset[a];
    int end   = g_offset[a + 1];

    float accR[NR];
    float accV[NA * 3];
    float accQ[NA * 6];
    #pragma unroll
    for (int k = 0; k < NR; k++) accR[k] = 0.0f;
    #pragma unroll
    for (int k = 0; k < NA * 3; k++) accV[k] = 0.0f;
    #pragma unroll
    for (int k = 0; k < NA * 6; k++) accQ[k] = 0.0f;

    float4 ra; float2 rb;
    if (start < end) { ra = g_ra[start]; rb = g_rb[start]; }

    for (int i = start; i < end; i++) {
        float4 ra_n; float2 rb_n;
        if (i + 1 < end) { ra_n = g_ra[i + 1]; rb_n = g_rb[i + 1]; }

        float x = ra.x, cut = ra.y;
        float ux = ra.z, uy = ra.w, uz = rb.x;
        int pair = __float_as_int(rb.y);

        // Chebyshev recurrence is linear -> seed with cut to get cut*T_k free
        float T[NR];
        T[0] = cut;
        T[1] = x * cut;
        float x2 = 2.0f * x;
        #pragma unroll
        for (int k = 2; k < NR; k++) T[k] = fmaf(x2, T[k - 1], -T[k - 2]);

        // radial: 11 outputs x 11 basis
        #pragma unroll
        for (int n = 0; n < NR; n++) {
            float acc = accR[n];
            #pragma unroll
            for (int b = 0; b < NR; b++)
                acc = fmaf(T[b], crs[(b * NR + n) * 16 + pair], acc);
            accR[n] = acc;
        }

        // angular features: 7 outputs x 9 basis
        float af[NA];
        #pragma unroll
        for (int n = 0; n < NA; n++) {
            float acc = 0.0f;
            #pragma unroll
            for (int b = 0; b < BA; b++)
                acc = fmaf(T[b], cas[(b * NA + n) * 16 + pair], acc);
            af[n] = acc;
        }

        float qxx = fmaf(1.5f * ux, ux, -0.5f);
        float qyy = fmaf(1.5f * uy, uy, -0.5f);
        float qzz = fmaf(1.5f * uz, uz, -0.5f);
        float qxy = 1.5f * ux * uy;
        float qxz = 1.5f * ux * uz;
        float qyz = 1.5f * uy * uz;

        #pragma unroll
        for (int n = 0; n < NA; n++) {
            float f = af[n];
            accV[n * 3 + 0] = fmaf(f, ux, accV[n * 3 + 0]);
            accV[n * 3 + 1] = fmaf(f, uy, accV[n * 3 + 1]);
            accV[n * 3 + 2] = fmaf(f, uz, accV[n * 3 + 2]);
            accQ[n * 6 + 0] = fmaf(f, qxx, accQ[n * 6 + 0]);
            accQ[n * 6 + 1] = fmaf(f, qyy, accQ[n * 6 + 1]);
            accQ[n * 6 + 2] = fmaf(f, qzz, accQ[n * 6 + 2]);
            accQ[n * 6 + 3] = fmaf(f, qxy, accQ[n * 6 + 3]);
            accQ[n * 6 + 4] = fmaf(f, qxz, accQ[n * 6 + 4]);
            accQ[n * 6 + 5] = fmaf(f, qyz, accQ[n * 6 + 5]);
        }

        ra = ra_n; rb = rb_n;
    }

    float* o = out + a * 25;
    #pragma unroll
    for (int n = 0; n < NR; n++) o[n] = accR[n];
    #pragma unroll
    for (int n = 0; n < NA; n++) {
        float vx = accV[n * 3 + 0], vy = accV[n * 3 + 1], vz = accV[n * 3 + 2];
        o[11 + n] = vx * vx + vy * vy + vz * vz;
    }
    #pragma unroll
    for (int n = 0; n < NA; n++) {
        float xx = accQ[n * 6 + 0], yy = accQ[n * 6 + 1], zz = accQ[n * 6 + 2];
        float xy = accQ[n * 6 + 3], xz = accQ[n * 6 + 4], yz = accQ[n * 6 + 5];
        o[18 + n] = xx * xx + yy * yy + zz * zz
                  + 2.0f * (xy * xy + xz * xz + yz * yz);
    }
}

extern "C" void kernel_launch(void* const* d_in, const int* in_sizes, int n_in,
                              void* d_out, int out_size)
{
    const void*  edge_index  = d_in[0];
    const float* edge_length = (const float*)d_in[1];
    const float* edge_vec    = (const float*)d_in[2];
    // d_in[3] = num_atoms scalar (unused; N derived from out_size)
    const void*  types       = d_in[4];
    const float* c_radial    = (const float*)d_in[5];
    const float* c_angular   = (const float*)d_in[6];

    int E = in_sizes[1];        // edge_length element count
    int N = out_size / 25;

    detect_dtype_kernel<<<1, 1>>>((const int*)edge_index);
    zero_counts_kernel<<<(N + 255) / 256, 256>>>(N);
    hist_kernel<<<(E + 255) / 256, 256>>>(edge_index, E);
    scan_kernel<<<1, 1024>>>(N);
    scatter_kernel<<<(E + 255) / 256, 256>>>(edge_index, edge_length, edge_vec,
                                             types, E);
    gather_kernel<<<(N + 127) / 128, 128>>>((float*)d_out, c_radial, c_angular, N);
}

// round 5
// speedup vs baseline: 1.7330x; 1.7330x over previous
#include <cuda_runtime.h>
#include <cuda_bf16.h>

// NEP descriptor R4: counting-sort + register gather-reduce.
// R3->R4: replace 81us single-block scan with 3-step device-wide scan.

#define NUM_TYPES 4
#define NR 11          // N_MAX_RADIAL+1 (= BASIS_RADIAL+1)
#define NA 7           // N_MAX_ANGULAR+1
#define BA 9           // BASIS_ANGULAR+1
#define MAX_ATOMS 50176
#define EMAX 1000000
#define SCAN_BLK 256
#define MAX_BLOCKS 1024   // supports N up to 262144

__device__ int    g_count[MAX_ATOMS];
__device__ int    g_offset[MAX_ATOMS + 1];
__device__ int    g_cursor[MAX_ATOMS];
__device__ int    g_bsum[MAX_BLOCKS];
__device__ int    g_bbase[MAX_BLOCKS];
__device__ float4 g_ra[EMAX];   // (x, cut, ux, uy)
__device__ float2 g_rb[EMAX];   // (uz, pair-as-bits)
__device__ int    g_idx64;      // 1 if edge_index/types are int64

__global__ void detect_dtype_kernel(const int* __restrict__ ei32) {
    // int64 indices < 2^31 viewed as int32 pairs: every odd word is 0.
    int ok = 1;
    #pragma unroll
    for (int k = 1; k < 32; k += 2)
        if (ei32[k] != 0) ok = 0;
    g_idx64 = ok;
}

__global__ void zero_counts_kernel(int N) {
    int i = blockIdx.x * blockDim.x + threadIdx.x;
    if (i < N) g_count[i] = 0;
}

__global__ void hist_kernel(const void* __restrict__ edge_index, int E) {
    int e = blockIdx.x * blockDim.x + threadIdx.x;
    if (e >= E) return;
    int row = g_idx64 ? (int)((const long long*)edge_index)[e]
                      : ((const int*)edge_index)[e];
    atomicAdd(&g_count[row], 1);
}

// Step 1: per-block sums of counts.
__global__ __launch_bounds__(SCAN_BLK)
void block_sum_kernel(int N) {
    __shared__ int wsum[SCAN_BLK / 32];
    int i = blockIdx.x * SCAN_BLK + threadIdx.x;
    int v = (i < N) ? g_count[i] : 0;
    #pragma unroll
    for (int o = 16; o > 0; o >>= 1)
        v += __shfl_down_sync(0xFFFFFFFFu, v, o);
    int lane = threadIdx.x & 31, wid = threadIdx.x >> 5;
    if (lane == 0) wsum[wid] = v;
    __syncthreads();
    if (wid == 0) {
        int s = (lane < SCAN_BLK / 32) ? wsum[lane] : 0;
        #pragma unroll
        for (int o = 16; o > 0; o >>= 1)
            s += __shfl_down_sync(0xFFFFFFFFu, s, o);
        if (lane == 0) g_bsum[blockIdx.x] = s;
    }
}

// Step 2: exclusive scan of the (<=1024) block sums, single block.
__global__ __launch_bounds__(1024)
void scan_bsums_kernel(int nblocks, int N) {
    __shared__ int wsum[32];
    int t = threadIdx.x;
    int lane = t & 31, wid = t >> 5;
    int v = (t < nblocks) ? g_bsum[t] : 0;
    int inc = v;
    #pragma unroll
    for (int o = 1; o < 32; o <<= 1) {
        int n = __shfl_up_sync(0xFFFFFFFFu, inc, o);
        if (lane >= o) inc += n;
    }
    if (lane == 31) wsum[wid] = inc;
    __syncthreads();
    if (wid == 0) {
        int w = (lane < 32) ? wsum[lane] : 0;
        #pragma unroll
        for (int o = 1; o < 32; o <<= 1) {
            int n = __shfl_up_sync(0xFFFFFFFFu, w, o);
            if (lane >= o) w += n;
        }
        wsum[lane] = w;
    }
    __syncthreads();
    int excl = inc - v + (wid > 0 ? wsum[wid - 1] : 0);
    if (t < nblocks) g_bbase[t] = excl;
    if (t == nblocks - 1) g_offset[N] = excl + v;   // grand total
}

// Step 3: per-block exclusive scan + base -> offsets & cursors.
__global__ __launch_bounds__(SCAN_BLK)
void offsets_kernel(int N) {
    __shared__ int wsum[SCAN_BLK / 32];
    int i = blockIdx.x * SCAN_BLK + threadIdx.x;
    int lane = threadIdx.x & 31, wid = threadIdx.x >> 5;
    int v = (i < N) ? g_count[i] : 0;
    int inc = v;
    #pragma unroll
    for (int o = 1; o < 32; o <<= 1) {
        int n = __shfl_up_sync(0xFFFFFFFFu, inc, o);
        if (lane >= o) inc += n;
    }
    if (lane == 31) wsum[wid] = inc;
    __syncthreads();
    if (wid == 0) {
        int w = (lane < SCAN_BLK / 32) ? wsum[lane] : 0;
        #pragma unroll
        for (int o = 1; o < 32; o <<= 1) {
            int n = __shfl_up_sync(0xFFFFFFFFu, w, o);
            if (lane >= o) w += n;
        }
        if (lane < SCAN_BLK / 32) wsum[lane] = w;
    }
    __syncthreads();
    int excl = inc - v + (wid > 0 ? wsum[wid - 1] : 0) + g_bbase[blockIdx.x];
    if (i < N) {
        g_offset[i] = excl;
        g_cursor[i] = excl;
    }
}

__global__ __launch_bounds__(256)
void scatter_kernel(const void* __restrict__ edge_index,
                    const float* __restrict__ edge_length,
                    const float* __restrict__ edge_vec,
                    const void* __restrict__ types,
                    int E)
{
    int e = blockIdx.x * blockDim.x + threadIdx.x;
    if (e >= E) return;

    int row, col, ti, tj;
    if (g_idx64) {
        const long long* ei = (const long long*)edge_index;
        const long long* ty = (const long long*)types;
        row = (int)ei[e];
        col = (int)ei[E + e];
        ti = (int)ty[row]; tj = (int)ty[col];
    } else {
        const int* ei = (const int*)edge_index;
        const int* ty = (const int*)types;
        row = ei[e];
        col = ei[E + e];
        ti = ty[row]; tj = ty[col];
    }
    int pair = ti * NUM_TYPES + tj;

    float d = edge_length[e];
    float s = d * 0.2f;                    // d / CUTOFF
    float x = 2.0f * s - 1.0f;
    float denom = 1.0f - s * s;
    float cut = (s < 1.0f) ? expf(1.0f - 1.0f / denom) : 0.0f;

    float vx = edge_vec[e * 3 + 0];
    float vy = edge_vec[e * 3 + 1];
    float vz = edge_vec[e * 3 + 2];
    float inv = 1.0f / fmaxf(d, 1e-8f);

    int pos = atomicAdd(&g_cursor[row], 1);
    g_ra[pos] = make_float4(x, cut, vx * inv, vy * inv);
    g_rb[pos] = make_float2(vz * inv, __int_as_float(pair));
}

__global__ __launch_bounds__(128)
void gather_kernel(float* __restrict__ out,
                   const float* __restrict__ c_radial,
                   const float* __restrict__ c_angular,
                   int N)
{
    // Shared coefficient tables, pair-minor: lanes with different pairs hit
    // distinct banks; same pair -> broadcast. Conflict-free.
    __shared__ float crs[NR * NR * 16];   // [(b*11+n)*16 + pair]
    __shared__ float cas[BA * NA * 16];   // [(b*7+n)*16 + pair]

    for (int i = threadIdx.x; i < 16 * NR * NR; i += blockDim.x) {
        int pair = i / (NR * NR);
        int nb   = i % (NR * NR);
        int n = nb / NR, b = nb % NR;
        crs[(b * NR + n) * 16 + pair] = c_radial[i];
    }
    for (int i = threadIdx.x; i < 16 * NA * BA; i += blockDim.x) {
        int pair = i / (NA * BA);
        int nb   = i % (NA * BA);
        int n = nb / BA, b = nb % BA;
        cas[(b * NA + n) * 16 + pair] = c_angular[i];
    }
    __syncthreads();

    int a = blockIdx.x * blockDim.x + threadIdx.x;
    if (a >= N) return;

    int start = g_offset[a];
    int end   = g_offset[a + 1];

    float accR[NR];
    float accV[NA * 3];
    float accQ[NA * 6];
    #pragma unroll
    for (int k = 0; k < NR; k++) accR[k] = 0.0f;
    #pragma unroll
    for (int k = 0; k < NA * 3; k++) accV[k] = 0.0f;
    #pragma unroll
    for (int k = 0; k < NA * 6; k++) accQ[k] = 0.0f;

    float4 ra; float2 rb;
    if (start < end) { ra = g_ra[start]; rb = g_rb[start]; }

    for (int i = start; i < end; i++) {
        float4 ra_n; float2 rb_n;
        if (i + 1 < end) { ra_n = g_ra[i + 1]; rb_n = g_rb[i + 1]; }

        float x = ra.x, cut = ra.y;
        float ux = ra.z, uy = ra.w, uz = rb.x;
        int pair = __float_as_int(rb.y);

        // Chebyshev recurrence is linear -> seed with cut to get cut*T_k free
        float T[NR];
        T[0] = cut;
        T[1] = x * cut;
        float x2 = 2.0f * x;
        #pragma unroll
        for (int k = 2; k < NR; k++) T[k] = fmaf(x2, T[k - 1], -T[k - 2]);

        // radial: 11 outputs x 11 basis
        #pragma unroll
        for (int n = 0; n < NR; n++) {
            float acc = accR[n];
            #pragma unroll
            for (int b = 0; b < NR; b++)
                acc = fmaf(T[b], crs[(b * NR + n) * 16 + pair], acc);
            accR[n] = acc;
        }

        // angular features: 7 outputs x 9 basis
        float af[NA];
        #pragma unroll
        for (int n = 0; n < NA; n++) {
            float acc = 0.0f;
            #pragma unroll
            for (int b = 0; b < BA; b++)
                acc = fmaf(T[b], cas[(b * NA + n) * 16 + pair], acc);
            af[n] = acc;
        }

        float qxx = fmaf(1.5f * ux, ux, -0.5f);
        float qyy = fmaf(1.5f * uy, uy, -0.5f);
        float qzz = fmaf(1.5f * uz, uz, -0.5f);
        float qxy = 1.5f * ux * uy;
        float qxz = 1.5f * ux * uz;
        float qyz = 1.5f * uy * uz;

        #pragma unroll
        for (int n = 0; n < NA; n++) {
            float f = af[n];
            accV[n * 3 + 0] = fmaf(f, ux, accV[n * 3 + 0]);
            accV[n * 3 + 1] = fmaf(f, uy, accV[n * 3 + 1]);
            accV[n * 3 + 2] = fmaf(f, uz, accV[n * 3 + 2]);
            accQ[n * 6 + 0] = fmaf(f, qxx, accQ[n * 6 + 0]);
            accQ[n * 6 + 1] = fmaf(f, qyy, accQ[n * 6 + 1]);
            accQ[n * 6 + 2] = fmaf(f, qzz, accQ[n * 6 + 2]);
            accQ[n * 6 + 3] = fmaf(f, qxy, accQ[n * 6 + 3]);
            accQ[n * 6 + 4] = fmaf(f, qxz, accQ[n * 6 + 4]);
            accQ[n * 6 + 5] = fmaf(f, qyz, accQ[n * 6 + 5]);
        }

        ra = ra_n; rb = rb_n;
    }

    float* o = out + a * 25;
    #pragma unroll
    for (int n = 0; n < NR; n++) o[n] = accR[n];
    #pragma unroll
    for (int n = 0; n < NA; n++) {
        float vx = accV[n * 3 + 0], vy = accV[n * 3 + 1], vz = accV[n * 3 + 2];
        o[11 + n] = vx * vx + vy * vy + vz * vz;
    }
    #pragma unroll
    for (int n = 0; n < NA; n++) {
        float xx = accQ[n * 6 + 0], yy = accQ[n * 6 + 1], zz = accQ[n * 6 + 2];
        float xy = accQ[n * 6 + 3], xz = accQ[n * 6 + 4], yz = accQ[n * 6 + 5];
        o[18 + n] = xx * xx + yy * yy + zz * zz
                  + 2.0f * (xy * xy + xz * xz + yz * yz);
    }
}

extern "C" void kernel_launch(void* const* d_in, const int* in_sizes, int n_in,
                              void* d_out, int out_size)
{
    const void*  edge_index  = d_in[0];
    const float* edge_length = (const float*)d_in[1];
    const float* edge_vec    = (const float*)d_in[2];
    // d_in[3] = num_atoms scalar (unused; N derived from out_size)
    const void*  types       = d_in[4];
    const float* c_radial    = (const float*)d_in[5];
    const float* c_angular   = (const float*)d_in[6];

    int E = in_sizes[1];        // edge_length element count
    int N = out_size / 25;
    int nblocks = (N + SCAN_BLK - 1) / SCAN_BLK;   // <= MAX_BLOCKS

    detect_dtype_kernel<<<1, 1>>>((const int*)edge_index);
    zero_counts_kernel<<<(N + 255) / 256, 256>>>(N);
    hist_kernel<<<(E + 255) / 256, 256>>>(edge_index, E);
    block_sum_kernel<<<nblocks, SCAN_BLK>>>(N);
    scan_bsums_kernel<<<1, 1024>>>(nblocks, N);
    offsets_kernel<<<nblocks, SCAN_BLK>>>(N);
    scatter_kernel<<<(E + 255) / 256, 256>>>(edge_index, edge_length, edge_vec,
                                             types, E);
    gather_kernel<<<(N + 127) / 128, 128>>>((float*)d_out, c_radial, c_angular, N);
}